// round 1
// baseline (speedup 1.0000x reference)
#include <cuda_runtime.h>
#include <cuda_bf16.h>
#include <math.h>

#define BB   2
#define LL   4096
#define DIM  2048
#define NST  64
#define RNK  128
#define PP   256
#define BL   (BB*LL)

// ---------------- scratch (static device globals; no allocs) ----------------
__device__ float g_xn[BL * DIM];      // 64 MB  normalized x
__device__ float g_proj[BL * PP];     //  8 MB  x_proj output (delta_r | B | C)
__device__ float g_delta[BL * DIM];   // 64 MB  softplus(dt)
__device__ float g_y[BL * DIM];       // 64 MB  y + x*D  (input to out_proj)

// ---------------- kernel 1: LayerNorm -> g_xn ----------------
__global__ void ln_kernel(const float* __restrict__ x,
                          const float* __restrict__ w,
                          const float* __restrict__ bta,
                          float* __restrict__ xn)
{
    __shared__ float red[2][8];
    const int row = blockIdx.x;
    const float* xr = x + (size_t)row * DIM;
    const int t = threadIdx.x;

    float4 v0 = ((const float4*)xr)[t];
    float4 v1 = ((const float4*)xr)[t + 256];
    float s = v0.x + v0.y + v0.z + v0.w + v1.x + v1.y + v1.z + v1.w;
    float q = v0.x*v0.x + v0.y*v0.y + v0.z*v0.z + v0.w*v0.w
            + v1.x*v1.x + v1.y*v1.y + v1.z*v1.z + v1.w*v1.w;

    #pragma unroll
    for (int o = 16; o; o >>= 1) {
        s += __shfl_xor_sync(0xffffffffu, s, o);
        q += __shfl_xor_sync(0xffffffffu, q, o);
    }
    const int lane = t & 31, wid = t >> 5;
    if (lane == 0) { red[0][wid] = s; red[1][wid] = q; }
    __syncthreads();
    if (t < 32) {
        s = (lane < 8) ? red[0][lane] : 0.f;
        q = (lane < 8) ? red[1][lane] : 0.f;
        #pragma unroll
        for (int o = 4; o; o >>= 1) {
            s += __shfl_xor_sync(0xffffffffu, s, o);
            q += __shfl_xor_sync(0xffffffffu, q, o);
        }
        if (lane == 0) { red[0][0] = s * (1.f/DIM); red[1][0] = q * (1.f/DIM); }
    }
    __syncthreads();
    const float mean = red[0][0];
    const float rstd = rsqrtf(red[1][0] - mean*mean + 1e-5f);

    float4 w0 = ((const float4*)w)[t],   w1 = ((const float4*)w)[t + 256];
    float4 b0 = ((const float4*)bta)[t], b1 = ((const float4*)bta)[t + 256];
    float4 o0, o1;
    o0.x = (v0.x - mean)*rstd*w0.x + b0.x;  o0.y = (v0.y - mean)*rstd*w0.y + b0.y;
    o0.z = (v0.z - mean)*rstd*w0.z + b0.z;  o0.w = (v0.w - mean)*rstd*w0.w + b0.w;
    o1.x = (v1.x - mean)*rstd*w1.x + b1.x;  o1.y = (v1.y - mean)*rstd*w1.y + b1.y;
    o1.z = (v1.z - mean)*rstd*w1.z + b1.z;  o1.w = (v1.w - mean)*rstd*w1.w + b1.w;
    float4* xo = (float4*)(xn + (size_t)row * DIM);
    xo[t] = o0;  xo[t + 256] = o1;
}

// ---------------- generic NT SGEMM: C[m,n] = sum_k A[m,k]*W[n,k] ----------------
// BM=BN=128, BK=16, 256 threads, 8x8 per thread. ACT: 0=none, 1=bias+softplus.
template<int ACT>
__global__ __launch_bounds__(256, 2)
void sgemm_nt(const float* __restrict__ A, int lda,
              const float* __restrict__ W, int ldw,
              float* __restrict__ C, int ldc,
              int K, const float* __restrict__ bias)
{
    __shared__ float As[16][128];
    __shared__ float Ws[16][128];
    const int bm = blockIdx.y * 128;
    const int bn = blockIdx.x * 128;
    const int tid = threadIdx.x;
    const int tx = tid & 15;        // n direction
    const int ty = tid >> 4;        // m direction

    float acc[8][8];
    #pragma unroll
    for (int i = 0; i < 8; i++)
        #pragma unroll
        for (int j = 0; j < 8; j++) acc[i][j] = 0.f;

    for (int k0 = 0; k0 < K; k0 += 16) {
        #pragma unroll
        for (int i = 0; i < 2; i++) {
            int idx = tid + i * 256;         // 0..511
            int m  = idx >> 2;
            int kq = idx & 3;
            float4 va = *(const float4*)&A[(size_t)(bm + m) * lda + k0 + kq*4];
            As[kq*4+0][m] = va.x; As[kq*4+1][m] = va.y;
            As[kq*4+2][m] = va.z; As[kq*4+3][m] = va.w;
            float4 vw = *(const float4*)&W[(size_t)(bn + m) * ldw + k0 + kq*4];
            Ws[kq*4+0][m] = vw.x; Ws[kq*4+1][m] = vw.y;
            Ws[kq*4+2][m] = vw.z; Ws[kq*4+3][m] = vw.w;
        }
        __syncthreads();
        #pragma unroll
        for (int kk = 0; kk < 16; kk++) {
            float4 a0 = *(const float4*)&As[kk][ty*8];
            float4 a1 = *(const float4*)&As[kk][ty*8 + 4];
            float4 b0 = *(const float4*)&Ws[kk][tx*8];
            float4 b1 = *(const float4*)&Ws[kk][tx*8 + 4];
            float ar[8] = {a0.x,a0.y,a0.z,a0.w,a1.x,a1.y,a1.z,a1.w};
            float br[8] = {b0.x,b0.y,b0.z,b0.w,b1.x,b1.y,b1.z,b1.w};
            #pragma unroll
            for (int i = 0; i < 8; i++)
                #pragma unroll
                for (int j = 0; j < 8; j++)
                    acc[i][j] = fmaf(ar[i], br[j], acc[i][j]);
        }
        __syncthreads();
    }

    #pragma unroll
    for (int i = 0; i < 8; i++) {
        const int m = bm + ty*8 + i;
        float* cr = C + (size_t)m * ldc + bn + tx*8;
        float vals[8];
        #pragma unroll
        for (int j = 0; j < 8; j++) {
            float v = acc[i][j];
            if (ACT == 1) {
                v += bias[bn + tx*8 + j];
                v = (v > 20.f) ? v : log1pf(expf(v));
            }
            vals[j] = v;
        }
        *(float4*)cr       = make_float4(vals[0], vals[1], vals[2], vals[3]);
        *(float4*)(cr + 4) = make_float4(vals[4], vals[5], vals[6], vals[7]);
    }
}

// ---------------- kernel 4: selective scan ----------------
// One warp per d-channel (2 states/lane), 8 d-channels per CTA.
// Chunks of 64 timesteps staged in SMEM. Writes y + x*D to g_y.
#define CHUNK 64
__global__ __launch_bounds__(256)
void scan_kernel(const float* __restrict__ proj,
                 const float* __restrict__ delta,
                 const float* __restrict__ xn,
                 const float* __restrict__ x,
                 const float* __restrict__ A_log,
                 const float* __restrict__ D_param,
                 float* __restrict__ y)
{
    __shared__ float Bs[CHUNK][NST];
    __shared__ float Cs[CHUNK][NST];
    __shared__ float dts[8][CHUNK];
    __shared__ float xns[8][CHUNK];
    __shared__ float xraw[8][CHUNK];
    __shared__ float ys[8][CHUNK];

    const int b  = blockIdx.y;
    const int d0 = blockIdx.x * 8;
    const int tid  = threadIdx.x;
    const int w    = tid >> 5;
    const int lane = tid & 31;
    const int d    = d0 + w;

    const float a0 = -expf(A_log[d * NST + 2*lane]);
    const float a1 = -expf(A_log[d * NST + 2*lane + 1]);
    const float Dd = D_param[d];
    float h0 = 0.f, h1 = 0.f;
    const int baseRow = b * LL;

    for (int l0 = 0; l0 < LL; l0 += CHUNK) {
        // stage B/C (shared across all d in CTA)
        for (int idx = tid; idx < CHUNK * 16; idx += 256) {
            int r  = idx >> 4;
            int c4 = (idx & 15) * 4;
            const float* pr = proj + (size_t)(baseRow + l0 + r) * PP;
            float4 vb = *(const float4*)(pr + RNK + c4);
            float4 vc = *(const float4*)(pr + RNK + NST + c4);
            Bs[r][c4+0] = vb.x; Bs[r][c4+1] = vb.y; Bs[r][c4+2] = vb.z; Bs[r][c4+3] = vb.w;
            Cs[r][c4+0] = vc.x; Cs[r][c4+1] = vc.y; Cs[r][c4+2] = vc.z; Cs[r][c4+3] = vc.w;
        }
        // stage per-d scalars
        for (int idx = tid; idx < 8 * CHUNK; idx += 256) {
            int li = idx >> 3, dl = idx & 7;
            size_t g = (size_t)(baseRow + l0 + li) * DIM + d0 + dl;
            dts[dl][li]  = delta[g];
            xns[dl][li]  = xn[g];
            xraw[dl][li] = x[g];
        }
        __syncthreads();

        #pragma unroll 4
        for (int li = 0; li < CHUNK; li++) {
            const float dt = dts[w][li];
            const float xv = xns[w][li];
            const float2 bv = *(const float2*)&Bs[li][2*lane];
            const float2 cv = *(const float2*)&Cs[li][2*lane];
            const float dA0 = __expf(dt * a0);
            const float dA1 = __expf(dt * a1);
            const float dtx = dt * xv;
            h0 = fmaf(dA0, h0, dtx * bv.x);
            h1 = fmaf(dA1, h1, dtx * bv.y);
            float p = fmaf(h1, cv.y, h0 * cv.x);
            p += __shfl_down_sync(0xffffffffu, p, 16);
            p += __shfl_down_sync(0xffffffffu, p, 8);
            p += __shfl_down_sync(0xffffffffu, p, 4);
            p += __shfl_down_sync(0xffffffffu, p, 2);
            p += __shfl_down_sync(0xffffffffu, p, 1);
            if (lane == 0) ys[w][li] = fmaf(xraw[w][li], Dd, p);
        }
        __syncthreads();

        for (int idx = tid; idx < 8 * CHUNK; idx += 256) {
            int li = idx >> 3, dl = idx & 7;
            y[(size_t)(baseRow + l0 + li) * DIM + d0 + dl] = ys[dl][li];
        }
        __syncthreads();
    }
}

// ---------------- launch ----------------
extern "C" void kernel_launch(void* const* d_in, const int* in_sizes, int n_in,
                              void* d_out, int out_size)
{
    const float* x         = (const float*)d_in[0];
    const float* norm_w    = (const float*)d_in[1];
    const float* norm_b    = (const float*)d_in[2];
    const float* x_proj_w  = (const float*)d_in[3];   // (256, 2048)
    const float* dt_proj_w = (const float*)d_in[4];   // (2048, 128)
    const float* dt_proj_b = (const float*)d_in[5];   // (2048,)
    const float* A_log     = (const float*)d_in[6];   // (2048, 64)
    const float* D_param   = (const float*)d_in[7];   // (2048,)
    const float* out_proj_w= (const float*)d_in[8];   // (2048, 2048)
    float* out = (float*)d_out;

    float *p_xn, *p_proj, *p_delta, *p_y;
    cudaGetSymbolAddress((void**)&p_xn,    g_xn);
    cudaGetSymbolAddress((void**)&p_proj,  g_proj);
    cudaGetSymbolAddress((void**)&p_delta, g_delta);
    cudaGetSymbolAddress((void**)&p_y,     g_y);

    // 1. LayerNorm
    ln_kernel<<<BL, 256>>>(x, norm_w, norm_b, p_xn);

    // 2. proj = xn @ x_proj_w^T   (M=8192, N=256, K=2048)
    sgemm_nt<0><<<dim3(PP/128, BL/128), 256>>>(p_xn, DIM, x_proj_w, DIM,
                                               p_proj, PP, DIM, nullptr);

    // 3. delta = softplus(delta_r @ dt_proj_w^T + b)  (M=8192, N=2048, K=128)
    sgemm_nt<1><<<dim3(DIM/128, BL/128), 256>>>(p_proj, PP, dt_proj_w, RNK,
                                                p_delta, DIM, RNK, dt_proj_b);

    // 4. selective scan -> g_y = y + x*D
    scan_kernel<<<dim3(DIM/8, BB), 256>>>(p_proj, p_delta, p_xn, x,
                                          A_log, D_param, p_y);

    // 5. out = (y + x*D) @ out_proj_w^T  (M=8192, N=2048, K=2048)
    sgemm_nt<0><<<dim3(DIM/128, BL/128), 256>>>(p_y, DIM, out_proj_w, DIM,
                                                out, DIM, DIM, nullptr);
}

// round 2
// speedup vs baseline: 1.5117x; 1.5117x over previous
#include <cuda_runtime.h>
#include <cuda_bf16.h>
#include <math.h>

#define BB   2
#define LL   4096
#define DIM  2048
#define NST  64
#define RNK  128
#define PP   256
#define BL   (BB*LL)

// ---------------- scratch (static device globals; no allocs) ----------------
__device__ float g_xn[BL * DIM];      // 64 MB  normalized x
__device__ float g_proj[BL * PP];     //  8 MB  x_proj output (delta_r | B | C)
__device__ float g_delta[BL * DIM];   // 64 MB  softplus(dt)
__device__ float g_y[BL * DIM];       // 64 MB  y + x*D  (input to out_proj)

// ---------------- kernel 1: LayerNorm -> g_xn ----------------
__global__ void ln_kernel(const float* __restrict__ x,
                          const float* __restrict__ w,
                          const float* __restrict__ bta,
                          float* __restrict__ xn)
{
    __shared__ float red[2][8];
    const int row = blockIdx.x;
    const float* xr = x + (size_t)row * DIM;
    const int t = threadIdx.x;

    float4 v0 = ((const float4*)xr)[t];
    float4 v1 = ((const float4*)xr)[t + 256];
    float s = v0.x + v0.y + v0.z + v0.w + v1.x + v1.y + v1.z + v1.w;
    float q = v0.x*v0.x + v0.y*v0.y + v0.z*v0.z + v0.w*v0.w
            + v1.x*v1.x + v1.y*v1.y + v1.z*v1.z + v1.w*v1.w;

    #pragma unroll
    for (int o = 16; o; o >>= 1) {
        s += __shfl_xor_sync(0xffffffffu, s, o);
        q += __shfl_xor_sync(0xffffffffu, q, o);
    }
    const int lane = t & 31, wid = t >> 5;
    if (lane == 0) { red[0][wid] = s; red[1][wid] = q; }
    __syncthreads();
    if (t < 32) {
        s = (lane < 8) ? red[0][lane] : 0.f;
        q = (lane < 8) ? red[1][lane] : 0.f;
        #pragma unroll
        for (int o = 4; o; o >>= 1) {
            s += __shfl_xor_sync(0xffffffffu, s, o);
            q += __shfl_xor_sync(0xffffffffu, q, o);
        }
        if (lane == 0) { red[0][0] = s * (1.f/DIM); red[1][0] = q * (1.f/DIM); }
    }
    __syncthreads();
    const float mean = red[0][0];
    const float rstd = rsqrtf(red[1][0] - mean*mean + 1e-5f);

    float4 w0 = ((const float4*)w)[t],   w1 = ((const float4*)w)[t + 256];
    float4 b0 = ((const float4*)bta)[t], b1 = ((const float4*)bta)[t + 256];
    float4 o0, o1;
    o0.x = (v0.x - mean)*rstd*w0.x + b0.x;  o0.y = (v0.y - mean)*rstd*w0.y + b0.y;
    o0.z = (v0.z - mean)*rstd*w0.z + b0.z;  o0.w = (v0.w - mean)*rstd*w0.w + b0.w;
    o1.x = (v1.x - mean)*rstd*w1.x + b1.x;  o1.y = (v1.y - mean)*rstd*w1.y + b1.y;
    o1.z = (v1.z - mean)*rstd*w1.z + b1.z;  o1.w = (v1.w - mean)*rstd*w1.w + b1.w;
    float4* xo = (float4*)(xn + (size_t)row * DIM);
    xo[t] = o0;  xo[t + 256] = o1;
}

// ---------------- generic NT SGEMM (fp32, FFMA) ----------------
// BM=BN=128, BK=16, 256 threads, 8x8 per thread. ACT: 0=none, 1=bias+softplus.
template<int ACT>
__global__ __launch_bounds__(256, 2)
void sgemm_nt(const float* __restrict__ A, int lda,
              const float* __restrict__ W, int ldw,
              float* __restrict__ C, int ldc,
              int K, const float* __restrict__ bias)
{
    __shared__ float As[16][128];
    __shared__ float Ws[16][128];
    const int bm = blockIdx.y * 128;
    const int bn = blockIdx.x * 128;
    const int tid = threadIdx.x;
    const int tx = tid & 15;        // n direction
    const int ty = tid >> 4;        // m direction

    float acc[8][8];
    #pragma unroll
    for (int i = 0; i < 8; i++)
        #pragma unroll
        for (int j = 0; j < 8; j++) acc[i][j] = 0.f;

    for (int k0 = 0; k0 < K; k0 += 16) {
        #pragma unroll
        for (int i = 0; i < 2; i++) {
            int idx = tid + i * 256;         // 0..511
            int m  = idx >> 2;
            int kq = idx & 3;
            float4 va = *(const float4*)&A[(size_t)(bm + m) * lda + k0 + kq*4];
            As[kq*4+0][m] = va.x; As[kq*4+1][m] = va.y;
            As[kq*4+2][m] = va.z; As[kq*4+3][m] = va.w;
            float4 vw = *(const float4*)&W[(size_t)(bn + m) * ldw + k0 + kq*4];
            Ws[kq*4+0][m] = vw.x; Ws[kq*4+1][m] = vw.y;
            Ws[kq*4+2][m] = vw.z; Ws[kq*4+3][m] = vw.w;
        }
        __syncthreads();
        #pragma unroll
        for (int kk = 0; kk < 16; kk++) {
            float4 a0 = *(const float4*)&As[kk][ty*8];
            float4 a1 = *(const float4*)&As[kk][ty*8 + 4];
            float4 b0 = *(const float4*)&Ws[kk][tx*8];
            float4 b1 = *(const float4*)&Ws[kk][tx*8 + 4];
            float ar[8] = {a0.x,a0.y,a0.z,a0.w,a1.x,a1.y,a1.z,a1.w};
            float br[8] = {b0.x,b0.y,b0.z,b0.w,b1.x,b1.y,b1.z,b1.w};
            #pragma unroll
            for (int i = 0; i < 8; i++)
                #pragma unroll
                for (int j = 0; j < 8; j++)
                    acc[i][j] = fmaf(ar[i], br[j], acc[i][j]);
        }
        __syncthreads();
    }

    #pragma unroll
    for (int i = 0; i < 8; i++) {
        const int m = bm + ty*8 + i;
        float* cr = C + (size_t)m * ldc + bn + tx*8;
        float vals[8];
        #pragma unroll
        for (int j = 0; j < 8; j++) {
            float v = acc[i][j];
            if (ACT == 1) {
                v += bias[bn + tx*8 + j];
                v = (v > 20.f) ? v : log1pf(expf(v));
            }
            vals[j] = v;
        }
        *(float4*)cr       = make_float4(vals[0], vals[1], vals[2], vals[3]);
        *(float4*)(cr + 4) = make_float4(vals[4], vals[5], vals[6], vals[7]);
    }
}

// ---------------- TF32 tensor-core NT GEMM: C[m,n] = sum_k A[m,k]*W[n,k] ----
// BM=BN=128, BK=32, 256 threads = 8 warps (4 along M x 2 along N).
// Warp tile 32(M) x 64(N) = 2x8 m16n8k8 MMAs.
__device__ __forceinline__ unsigned f2tf32(float f) {
    unsigned r;
    asm("cvt.rna.tf32.f32 %0, %1;" : "=r"(r) : "f"(f));
    return r;
}

__global__ __launch_bounds__(256, 2)
void tgemm_tf32(const float* __restrict__ A,
                const float* __restrict__ W,
                float* __restrict__ C,
                int lda, int ldw, int ldc, int K)
{
    // [row][k] layout, pitch 36 floats (pad 4): staging stores and fragment
    // loads both bank-conflict-free.
    __shared__ float As[128][36];
    __shared__ float Ws[128][36];

    const int bm = blockIdx.y * 128;
    const int bn = blockIdx.x * 128;
    const int tid  = threadIdx.x;
    const int lane = tid & 31;
    const int wid  = tid >> 5;
    const int wm = wid & 3;          // warp M index (0..3)
    const int wn = wid >> 2;         // warp N index (0..1)
    const int g  = lane >> 2;        // groupID 0..7
    const int tg = lane & 3;         // thread-in-group 0..3

    const int stage_m  = tid >> 3;         // 0..31... no: 256/8 = 32 rows/pass
    const int stage_kq = (tid & 7) * 4;    // k quad offset

    float acc[2][8][4];
    #pragma unroll
    for (int i = 0; i < 2; i++)
        #pragma unroll
        for (int j = 0; j < 8; j++)
            #pragma unroll
            for (int v = 0; v < 4; v++) acc[i][j][v] = 0.f;

    for (int k0 = 0; k0 < K; k0 += 32) {
        // stage 128 rows x 32 k of A and W; 256 threads, 4 passes each
        #pragma unroll
        for (int p = 0; p < 4; p++) {
            int m = stage_m + p * 32;
            float4 va = *(const float4*)&A[(size_t)(bm + m) * lda + k0 + stage_kq];
            float4 vw = *(const float4*)&W[(size_t)(bn + m) * ldw + k0 + stage_kq];
            As[m][stage_kq+0] = __uint_as_float(f2tf32(va.x));
            As[m][stage_kq+1] = __uint_as_float(f2tf32(va.y));
            As[m][stage_kq+2] = __uint_as_float(f2tf32(va.z));
            As[m][stage_kq+3] = __uint_as_float(f2tf32(va.w));
            Ws[m][stage_kq+0] = __uint_as_float(f2tf32(vw.x));
            Ws[m][stage_kq+1] = __uint_as_float(f2tf32(vw.y));
            Ws[m][stage_kq+2] = __uint_as_float(f2tf32(vw.z));
            Ws[m][stage_kq+3] = __uint_as_float(f2tf32(vw.w));
        }
        __syncthreads();

        #pragma unroll
        for (int kk = 0; kk < 4; kk++) {
            const int kb = kk * 8;
            unsigned a[2][4], b[8][2];
            #pragma unroll
            for (int mt = 0; mt < 2; mt++) {
                const int mr = wm * 32 + mt * 16;
                a[mt][0] = __float_as_uint(As[mr + g    ][kb + tg    ]);
                a[mt][1] = __float_as_uint(As[mr + g + 8][kb + tg    ]);
                a[mt][2] = __float_as_uint(As[mr + g    ][kb + tg + 4]);
                a[mt][3] = __float_as_uint(As[mr + g + 8][kb + tg + 4]);
            }
            #pragma unroll
            for (int nt = 0; nt < 8; nt++) {
                const int nr = wn * 64 + nt * 8 + g;
                b[nt][0] = __float_as_uint(Ws[nr][kb + tg    ]);
                b[nt][1] = __float_as_uint(Ws[nr][kb + tg + 4]);
            }
            #pragma unroll
            for (int mt = 0; mt < 2; mt++)
                #pragma unroll
                for (int nt = 0; nt < 8; nt++) {
                    asm volatile(
                        "mma.sync.aligned.m16n8k8.row.col.f32.tf32.tf32.f32 "
                        "{%0,%1,%2,%3}, {%4,%5,%6,%7}, {%8,%9}, {%0,%1,%2,%3};"
                        : "+f"(acc[mt][nt][0]), "+f"(acc[mt][nt][1]),
                          "+f"(acc[mt][nt][2]), "+f"(acc[mt][nt][3])
                        : "r"(a[mt][0]), "r"(a[mt][1]), "r"(a[mt][2]), "r"(a[mt][3]),
                          "r"(b[nt][0]), "r"(b[nt][1]));
                }
        }
        __syncthreads();
    }

    // epilogue: c0,c1 at (row, 2*tg), (row, 2*tg+1); c2,c3 at row+8
    #pragma unroll
    for (int mt = 0; mt < 2; mt++) {
        #pragma unroll
        for (int nt = 0; nt < 8; nt++) {
            const int row = bm + wm * 32 + mt * 16 + g;
            const int col = bn + wn * 64 + nt * 8 + 2 * tg;
            *(float2*)&C[(size_t)row * ldc + col] =
                make_float2(acc[mt][nt][0], acc[mt][nt][1]);
            *(float2*)&C[(size_t)(row + 8) * ldc + col] =
                make_float2(acc[mt][nt][2], acc[mt][nt][3]);
        }
    }
}

// ---------------- kernel 4: selective scan ----------------
#define CHUNK 64
__global__ __launch_bounds__(256)
void scan_kernel(const float* __restrict__ proj,
                 const float* __restrict__ delta,
                 const float* __restrict__ xn,
                 const float* __restrict__ x,
                 const float* __restrict__ A_log,
                 const float* __restrict__ D_param,
                 float* __restrict__ y)
{
    __shared__ float Bs[CHUNK][NST];
    __shared__ float Cs[CHUNK][NST];
    __shared__ float dts[8][CHUNK];
    __shared__ float xns[8][CHUNK];
    __shared__ float xraw[8][CHUNK];
    __shared__ float ys[8][CHUNK];

    const int b  = blockIdx.y;
    const int d0 = blockIdx.x * 8;
    const int tid  = threadIdx.x;
    const int w    = tid >> 5;
    const int lane = tid & 31;
    const int d    = d0 + w;

    const float a0 = -expf(A_log[d * NST + 2*lane]);
    const float a1 = -expf(A_log[d * NST + 2*lane + 1]);
    const float Dd = D_param[d];
    float h0 = 0.f, h1 = 0.f;
    const int baseRow = b * LL;

    for (int l0 = 0; l0 < LL; l0 += CHUNK) {
        for (int idx = tid; idx < CHUNK * 16; idx += 256) {
            int r  = idx >> 4;
            int c4 = (idx & 15) * 4;
            const float* pr = proj + (size_t)(baseRow + l0 + r) * PP;
            float4 vb = *(const float4*)(pr + RNK + c4);
            float4 vc = *(const float4*)(pr + RNK + NST + c4);
            Bs[r][c4+0] = vb.x; Bs[r][c4+1] = vb.y; Bs[r][c4+2] = vb.z; Bs[r][c4+3] = vb.w;
            Cs[r][c4+0] = vc.x; Cs[r][c4+1] = vc.y; Cs[r][c4+2] = vc.z; Cs[r][c4+3] = vc.w;
        }
        for (int idx = tid; idx < 8 * CHUNK; idx += 256) {
            int li = idx >> 3, dl = idx & 7;
            size_t gidx = (size_t)(baseRow + l0 + li) * DIM + d0 + dl;
            dts[dl][li]  = delta[gidx];
            xns[dl][li]  = xn[gidx];
            xraw[dl][li] = x[gidx];
        }
        __syncthreads();

        #pragma unroll 4
        for (int li = 0; li < CHUNK; li++) {
            const float dt = dts[w][li];
            const float xv = xns[w][li];
            const float2 bv = *(const float2*)&Bs[li][2*lane];
            const float2 cv = *(const float2*)&Cs[li][2*lane];
            const float dA0 = __expf(dt * a0);
            const float dA1 = __expf(dt * a1);
            const float dtx = dt * xv;
            h0 = fmaf(dA0, h0, dtx * bv.x);
            h1 = fmaf(dA1, h1, dtx * bv.y);
            float p = fmaf(h1, cv.y, h0 * cv.x);
            p += __shfl_down_sync(0xffffffffu, p, 16);
            p += __shfl_down_sync(0xffffffffu, p, 8);
            p += __shfl_down_sync(0xffffffffu, p, 4);
            p += __shfl_down_sync(0xffffffffu, p, 2);
            p += __shfl_down_sync(0xffffffffu, p, 1);
            if (lane == 0) ys[w][li] = fmaf(xraw[w][li], Dd, p);
        }
        __syncthreads();

        for (int idx = tid; idx < 8 * CHUNK; idx += 256) {
            int li = idx >> 3, dl = idx & 7;
            y[(size_t)(baseRow + l0 + li) * DIM + d0 + dl] = ys[dl][li];
        }
        __syncthreads();
    }
}

// ---------------- launch ----------------
extern "C" void kernel_launch(void* const* d_in, const int* in_sizes, int n_in,
                              void* d_out, int out_size)
{
    const float* x         = (const float*)d_in[0];
    const float* norm_w    = (const float*)d_in[1];
    const float* norm_b    = (const float*)d_in[2];
    const float* x_proj_w  = (const float*)d_in[3];   // (256, 2048)
    const float* dt_proj_w = (const float*)d_in[4];   // (2048, 128)
    const float* dt_proj_b = (const float*)d_in[5];   // (2048,)
    const float* A_log     = (const float*)d_in[6];   // (2048, 64)
    const float* D_param   = (const float*)d_in[7];   // (2048,)
    const float* out_proj_w= (const float*)d_in[8];   // (2048, 2048)
    float* out = (float*)d_out;

    float *p_xn, *p_proj, *p_delta, *p_y;
    cudaGetSymbolAddress((void**)&p_xn,    g_xn);
    cudaGetSymbolAddress((void**)&p_proj,  g_proj);
    cudaGetSymbolAddress((void**)&p_delta, g_delta);
    cudaGetSymbolAddress((void**)&p_y,     g_y);

    // 1. LayerNorm
    ln_kernel<<<BL, 256>>>(x, norm_w, norm_b, p_xn);

    // 2. proj = xn @ x_proj_w^T   (M=8192, N=256, K=2048)  [fp32: feeds scan]
    sgemm_nt<0><<<dim3(PP/128, BL/128), 256>>>(p_xn, DIM, x_proj_w, DIM,
                                               p_proj, PP, DIM, nullptr);

    // 3. delta = softplus(delta_r @ dt_proj_w^T + b)  (M=8192, N=2048, K=128)
    sgemm_nt<1><<<dim3(DIM/128, BL/128), 256>>>(p_proj, PP, dt_proj_w, RNK,
                                                p_delta, DIM, RNK, dt_proj_b);

    // 4. selective scan -> g_y = y + x*D
    scan_kernel<<<dim3(DIM/8, BB), 256>>>(p_proj, p_delta, p_xn, x,
                                          A_log, D_param, p_y);

    // 5. out = (y + x*D) @ out_proj_w^T  (M=8192, N=2048, K=2048) [TF32 tensor]
    tgemm_tf32<<<dim3(DIM/128, BL/128), 256>>>(p_y, out_proj_w, out,
                                               DIM, DIM, DIM, DIM);
}